// round 12
// baseline (speedup 1.0000x reference)
#include <cuda_runtime.h>
#include <cuda_fp16.h>
#include <cstdint>

#define B_   32
#define T_   256
#define N_   4096
#define D_   256
#define M_   (B_ * T_)
#define EPSF 1e-6f
#define DECF 0.97f

// ---------------- scratch (device globals; no allocation) ----------------
__device__ float g_CS[M_];
__device__ float g_Cc[M_];
__device__ float g_U [M_ * D_];
__device__ float g_S [2LL * B_ * T_ * T_];      // 2 split-K partials of 65536*scores
__device__ float g_A [2LL * M_ * D_];           // 2 split-K partials of a*
__device__ float g_O [2LL * M_ * D_];           // 2 split-K partials of G3
__device__ float g_DEC[T_];                     // 0.97^L / 65536 (gemm_nn only)

// fp16 operands; scalings: v,Dx x16; Dy,E x64; P,x x256; y x1024
__device__ __half g_Vf [M_ * D_];                             // 16*emb[idx]
__device__ __half g_DxH[N_ * D_];                             // 16*Dx
__device__ __half g_DyH[N_ * D_];                             // 64*Dy
__device__ __half g_EH [D_ * N_];                             // 64*E
__device__ __half g_Af [M_ * D_];                             // LN(a*) fp16
__device__ __half g_Xf [(long long)M_ * N_];                  // 256*x fp16
__device__ __half g_Yf [(long long)M_ * N_];                  // 256*P, then 1024*y fp16

// ---------------- PTX helpers (baseline ISA only) ----------------
__device__ __forceinline__ uint32_t smem_u32(const void* p) {
    uint32_t a;
    asm("{ .reg .u64 t; cvta.to.shared.u64 t, %1; cvt.u32.u64 %0, t; }" : "=r"(a) : "l"(p));
    return a;
}
__device__ __forceinline__ void cp16(uint32_t so, const void* g) {
    asm volatile("cp.async.cg.shared.global [%0], [%1], 16;" :: "r"(so), "l"(g));
}
__device__ __forceinline__ void cp_commit() {
    asm volatile("cp.async.commit_group;" ::: "memory");
}
template <int NN>
__device__ __forceinline__ void cp_wait() {
    asm volatile("cp.async.wait_group %0;" :: "n"(NN) : "memory");
}
__device__ __forceinline__ void ldsm_x4(uint32_t* f, uint32_t a) {
    asm volatile("ldmatrix.sync.aligned.m8n8.x4.shared.b16 {%0,%1,%2,%3}, [%4];"
        : "=r"(f[0]), "=r"(f[1]), "=r"(f[2]), "=r"(f[3]) : "r"(a));
}
__device__ __forceinline__ void mma_f16(float* c, const uint32_t* a, const uint32_t* b) {
    asm volatile("mma.sync.aligned.m16n8k16.row.col.f32.f16.f16.f32 "
        "{%0,%1,%2,%3}, {%4,%5,%6,%7}, {%8,%9}, {%0,%1,%2,%3};"
        : "+f"(c[0]), "+f"(c[1]), "+f"(c[2]), "+f"(c[3])
        : "r"(a[0]), "r"(a[1]), "r"(a[2]), "r"(a[3]), "r"(b[0]), "r"(b[1]));
}

// ------- HMMA NT GEMM: CTA 128x256, warp 64x64, 1 CTA/SM, 4-stage pipeline -----
enum { EPI_NONE = 0, EPI_RELUH = 1, EPI_RELUMULX = 2 };

// swizzled tiles, 64B rows; phys 16B-slot = g ^ ((r>>1)&3)
#define TILE_A  8192                 // 128 rows x 64B
#define TILE_BT 16384                // 256 rows x 64B
#define STAGE_B (TILE_A + TILE_BT)   // 24576
#define NSTG    4
#define SMEM_SZ (NSTG * STAGE_B)     // 98304

template <int EPI>
__global__ void __launch_bounds__(256, 1) mma_nt(
    const __half* __restrict__ Ah, const __half* __restrict__ Bh,
    float* __restrict__ Cf, __half* __restrict__ Ch,
    const __half* __restrict__ Xf,
    int Nd, int K, int kLen, long sA, long sB, long sC, long splitStride, int batches)
{
    extern __shared__ char smem[];
    const uint32_t sb = smem_u32(smem);
    const int tid  = threadIdx.x;
    const int lane = tid & 31;
    const int wid  = tid >> 5;
    const int wm   = wid >> 2;          // 0..1  -> m offset wm*64
    const int wn   = wid & 3;           // 0..3  -> n offset wn*64
    const int zz   = blockIdx.z;
    const int split = zz / batches;
    const int bz    = zz - split * batches;
    const long kOff = (long)split * kLen;
    const int bm = blockIdx.y * 128;
    const int bn = blockIdx.x * 256;

    float acc[4][8][4];
#pragma unroll
    for (int i = 0; i < 4; i++)
#pragma unroll
        for (int j = 0; j < 8; j++)
#pragma unroll
            for (int v = 0; v < 4; v++) acc[i][j][v] = 0.f;

    {
        const __half* Ahp = Ah + (long)bz * sA + (long)bm * K + kOff;
        const __half* Bhp = Bh + (long)bz * sB + (long)bn * K + kOff;

        const int qr0 = tid >> 2;             // row (0..63)
        const int qc0 = tid & 3;              // 16B group
        auto stage_load = [&](int stg, int k0) {
            uint32_t base = sb + stg * STAGE_B;
#pragma unroll
            for (int i = 0; i < 2; i++) {     // A: 128 rows
                int r = qr0 + i * 64;
                uint32_t so = (uint32_t)(r * 64 + ((qc0 ^ ((r >> 1) & 3)) * 16));
                cp16(base + so, Ahp + (long)r * K + k0 + qc0 * 8);
            }
#pragma unroll
            for (int i = 0; i < 4; i++) {     // B: 256 rows
                int r = qr0 + i * 64;
                uint32_t so = (uint32_t)(r * 64 + ((qc0 ^ ((r >> 1) & 3)) * 16));
                cp16(base + TILE_A + so, Bhp + (long)r * K + k0 + qc0 * 8);
            }
            cp_commit();
        };

        const int nC = kLen / 32;             // all callers have nC >= 8
        stage_load(0, 0);
        stage_load(1, 32);
        stage_load(2, 64);

        // per-lane ldsm logical positions
        const uint32_t aRow  = (uint32_t)(wm * 64 + (lane & 15));
        const uint32_t aColG = (uint32_t)(lane >> 4);
        const uint32_t bRow  = (uint32_t)(wn * 64 + ((lane >> 4) << 3) + (lane & 7));
        const uint32_t bColG = (uint32_t)((lane >> 3) & 1);
        const uint32_t sa  = (aRow >> 1) & 3;
        const uint32_t sbw = (bRow >> 1) & 3;
        uint32_t aoff[2], boff[2];
#pragma unroll
        for (int ks = 0; ks < 2; ks++) {
            aoff[ks] = aRow * 64 + (((ks * 2 + aColG) ^ sa) * 16);
            boff[ks] = bRow * 64 + (((ks * 2 + bColG) ^ sbw) * 16);
        }

        int stg = 0;
        for (int c = 0; c < nC; c++) {
            cp_wait<NSTG - 2>();              // chunk c complete
            __syncthreads();
            if (c + 3 < nC) {
                int ns = stg + 3; if (ns >= NSTG) ns -= NSTG;
                stage_load(ns, (c + 3) * 32);
            } else {
                cp_commit();   // empty group keeps wait accounting uniform
            }

            const uint32_t st = sb + stg * STAGE_B;
#pragma unroll
            for (int ks = 0; ks < 2; ks++) {
                uint32_t fA[4][4], fB[4][4];
#pragma unroll
                for (int ma = 0; ma < 4; ma++)
                    ldsm_x4(fA[ma], st + aoff[ks] + ma * 1024);
#pragma unroll
                for (int p = 0; p < 4; p++)
                    ldsm_x4(fB[p], st + TILE_A + boff[ks] + p * 1024);
#pragma unroll
                for (int ma = 0; ma < 4; ma++)
#pragma unroll
                    for (int na = 0; na < 8; na++)
                        mma_f16(acc[ma][na], fA[ma], &fB[na >> 1][2 * (na & 1)]);
            }
            stg = (stg == NSTG - 1) ? 0 : stg + 1;
        }
    }

    // ---- epilogue ----
    float* Cfo = (EPI == EPI_NONE) ? (Cf + split * splitStride + (long)bz * sC) : nullptr;
    unsigned short* Ho = (EPI != EPI_NONE) ? reinterpret_cast<unsigned short*>(Ch) : nullptr;
    const int gr = lane >> 2;          // 0..7
    const int gc = (lane & 3) * 2;
#pragma unroll
    for (int ma = 0; ma < 4; ma++) {
#pragma unroll
        for (int half = 0; half < 2; half++) {
            const int row = bm + wm * 64 + ma * 16 + gr + half * 8;
            float rs = 0.f;
#pragma unroll
            for (int na = 0; na < 8; na++) {
                const int col = bn + wn * 64 + na * 8 + gc;
                float v0 = acc[ma][na][half * 2 + 0];
                float v1 = acc[ma][na][half * 2 + 1];
                long off = (long)row * Nd + col;
                if (EPI == EPI_RELUH) {
                    // 256*P = relu(acc); fused row-sum (of 256*P) for L1 norm
                    v0 = fmaxf(v0, 0.f); v1 = fmaxf(v1, 0.f);
                    rs += v0 + v1;
                    ushort2 o = make_ushort2(__half_as_ushort(__float2half_rn(v0)),
                                             __half_as_ushort(__float2half_rn(v1)));
                    *reinterpret_cast<ushort2*>(Ho + off) = o;
                } else if (EPI == EPI_RELUMULX) {
                    // stored y = relu(64g) * (256x) / 16 = 1024*y_true
                    ushort2 xf = *reinterpret_cast<const ushort2*>(Xf + off);
                    float x0 = __half2float(__ushort_as_half(xf.x));
                    float x1 = __half2float(__ushort_as_half(xf.y));
                    v0 = fmaxf(v0, 0.f) * x0 * (1.f / 16.f);
                    v1 = fmaxf(v1, 0.f) * x1 * (1.f / 16.f);
                    ushort2 o = make_ushort2(__half_as_ushort(__float2half_rn(v0)),
                                             __half_as_ushort(__float2half_rn(v1)));
                    *reinterpret_cast<ushort2*>(Ho + off) = o;
                } else {
                    *reinterpret_cast<float2*>(Cfo + off) = make_float2(v0, v1);
                }
            }
            if (EPI == EPI_RELUH) {
                rs += __shfl_xor_sync(0xffffffffu, rs, 1);
                rs += __shfl_xor_sync(0xffffffffu, rs, 2);
                if ((lane & 3) == 0) atomicAdd(&g_CS[row], rs);
            }
        }
    }
}

// ---------------- SIMT NN GEMM: a* = (decayed S) @ U, split-K x2 ----------------
#define GBM 128
#define GBN 64
#define GBK 16
#define GTM 8
#define GTN 4

__global__ __launch_bounds__(256)
void gemm_nn(const float* __restrict__ A0, const float* __restrict__ A1,
             const float* __restrict__ B, float* __restrict__ C)
{
    const int zz = blockIdx.z;
    const int bz = zz & 31;          // batch
    const int split = zz >> 5;       // 0..1
    A0 += (long)bz * T_ * T_;
    A1 += (long)bz * T_ * T_;
    B  += (long)bz * T_ * D_;
    C  += (long)split * M_ * D_ + (long)bz * T_ * D_;
    const int bm = blockIdx.y * GBM;
    const int bn = blockIdx.x * GBN;

    __shared__ __align__(16) float As[GBK][GBM + 4];
    __shared__ __align__(16) float Bs[GBK][GBN + 4];

    const int tid = threadIdx.x;
    const int tx = tid & 15;
    const int ty = tid >> 4;

    float acc[GTM][GTN];
#pragma unroll
    for (int i = 0; i < GTM; i++)
#pragma unroll
        for (int j = 0; j < GTN; j++) acc[i][j] = 0.f;

    const int lr = tid >> 2;
    const int lk = (tid & 3) * 4;
    const int brow = tid >> 4;
    const int bcol = (tid & 15) * 4;

    const int kBeg = split * (T_ / 2);
    for (int k0 = kBeg; k0 < kBeg + T_ / 2; k0 += GBK) {
#pragma unroll
        for (int i = 0; i < 2; i++) {
            int r = lr + i * 64;
            int t = bm + r;
            long ao = (long)t * T_ + k0 + lk;
            float4 v = *reinterpret_cast<const float4*>(A0 + ao);
            float4 w = *reinterpret_cast<const float4*>(A1 + ao);
            float vv[4] = {v.x + w.x, v.y + w.y, v.z + w.z, v.w + w.w};
#pragma unroll
            for (int j = 0; j < 4; j++) {
                int L = t - (k0 + lk + j);
                As[lk + j][r] = (L > 0) ? vv[j] * g_DEC[L] : 0.f;   // /65536 baked into g_DEC
            }
        }
        {
            float4 v = *reinterpret_cast<const float4*>(B + (long)(k0 + brow) * D_ + bn + bcol);
            Bs[brow][bcol + 0] = v.x; Bs[brow][bcol + 1] = v.y;
            Bs[brow][bcol + 2] = v.z; Bs[brow][bcol + 3] = v.w;
        }
        __syncthreads();
#pragma unroll
        for (int kk = 0; kk < GBK; kk++) {
            float af[GTM], bf[GTN];
#pragma unroll
            for (int i = 0; i < GTM; i++) af[i] = As[kk][ty * GTM + i];
#pragma unroll
            for (int j = 0; j < GTN; j++) bf[j] = Bs[kk][tx * GTN + j];
#pragma unroll
            for (int i = 0; i < GTM; i++)
#pragma unroll
                for (int j = 0; j < GTN; j++)
                    acc[i][j] = fmaf(af[i], bf[j], acc[i][j]);
        }
        __syncthreads();
    }
#pragma unroll
    for (int i = 0; i < GTM; i++) {
        int row = bm + ty * GTM + i;
        long cbase = (long)row * D_ + bn + tx * GTN;
        *reinterpret_cast<float4*>(C + cbase) = make_float4(acc[i][0], acc[i][1], acc[i][2], acc[i][3]);
    }
}

// ---------------- elementwise / scan / LN kernels ----------------
__device__ __forceinline__ float blockReduceSum256(float v) {
    __shared__ float sh[8];
    __syncthreads();
    int lane = threadIdx.x & 31;
    int w = threadIdx.x >> 5;
#pragma unroll
    for (int o = 16; o > 0; o >>= 1) v += __shfl_down_sync(0xffffffffu, v, o);
    if (lane == 0) sh[w] = v;
    __syncthreads();
    if (w == 0) {
        float t = (lane < 8) ? sh[lane] : 0.f;
#pragma unroll
        for (int o = 4; o > 0; o >>= 1) t += __shfl_down_sync(0xffffffffu, t, o);
        if (lane == 0) sh[0] = t;
    }
    __syncthreads();
    return sh[0];
}

// fused conversions: Dx x16, Dy x64, E x64 -> fp16 single; + g_DEC init
__global__ void conv_all_kernel(const float* __restrict__ Dx, const float* __restrict__ Dy,
                                const float* __restrict__ E)
{
    int blk = blockIdx.x;
    const float* src;
    __half* hi;
    float scale;
    int local;
    if (blk < 1024)      { src = Dx; hi = g_DxH; scale = 16.f; local = blk; }
    else if (blk < 2048) { src = Dy; hi = g_DyH; scale = 64.f; local = blk - 1024; }
    else                 { src = E;  hi = g_EH;  scale = 64.f; local = blk - 2048; }
    long i = (long)local * 256 + threadIdx.x;
    float4 v = reinterpret_cast<const float4*>(src)[i];
    ushort4 o = make_ushort4(
        __half_as_ushort(__float2half_rn(v.x * scale)),
        __half_as_ushort(__float2half_rn(v.y * scale)),
        __half_as_ushort(__float2half_rn(v.z * scale)),
        __half_as_ushort(__float2half_rn(v.w * scale)));
    reinterpret_cast<ushort4*>(hi)[i] = o;
    if (blk == 0 && threadIdx.x == 0) {
        float d = 1.f;
        for (int t = 0; t < T_; t++) { g_DEC[t] = d * (1.f / 65536.f); d *= DECF; }
    }
}

// gather 16*emb[idx] -> fp16 single, and zero g_CS
__global__ void gatherconv_kernel(const float* __restrict__ emb, const int* __restrict__ idx)
{
    int m = blockIdx.x;
    int t = threadIdx.x;   // 64 threads, float4 each
    if (t == 0) g_CS[m] = 0.f;
    float4 v = *reinterpret_cast<const float4*>(emb + (long)idx[m] * D_ + t * 4);
    ushort4 o = make_ushort4(
        __half_as_ushort(__float2half_rn(v.x * 16.f)),
        __half_as_ushort(__float2half_rn(v.y * 16.f)),
        __half_as_ushort(__float2half_rn(v.z * 16.f)),
        __half_as_ushort(__float2half_rn(v.w * 16.f)));
    reinterpret_cast<ushort4*>(g_Vf)[(long)m * (D_ / 4) + t] = o;
}

__global__ void screc_kernel() {
    __shared__ float cs[B_ * T_];     // [t][b] layout, conflict-free
    for (int i = threadIdx.x; i < B_ * T_; i += 256) {
        int t = i >> 5, b = i & 31;
        cs[t * 32 + b] = g_CS[b * T_ + t] * (1.f / 256.f);   // unscale 256*P
    }
    __syncthreads();
    if (threadIdx.x < B_) {
        int b = threadIdx.x;
        float sprev = 0.f;
        for (int t = 0; t < T_; t++) {
            float sumx = __fdividef(sprev, sprev + EPSF);
            float s = DECF * sumx + cs[t * 32 + b];
            g_Cc[b * T_ + t] = __fdividef(1.f, s + EPSF);
            sprev = s;
        }
    }
}

// scan on 256-scaled values (linear in scale): X = 256*x
__global__ void xrecur_kernel() {
    int b = blockIdx.y;
    int n = blockIdx.x * 256 + threadIdx.x;
    __shared__ float sc[T_];
    sc[threadIdx.x] = g_Cc[b * T_ + threadIdx.x];
    __syncthreads();
    float X = 0.f;
    long base = (long)b * T_ * N_ + n;
    for (int t = 0; t < T_; t++) {
        float p = __half2float(g_Yf[base + (long)t * N_]);    // 256*P
        X = (DECF * X + p) * sc[t];
        g_Xf[base + (long)t * N_] = __float2half_rn(X);
    }
}

// OUT: 0 = fp32, 1 = fp16 single
template <int OUT, int NPART>
__global__ void ln_rows(const float* __restrict__ in, float* __restrict__ outf,
                        unsigned short* __restrict__ oh,
                        const int* __restrict__ gidx, float inscale)
{
    int m = blockIdx.x;
    long r = gidx ? (long)gidx[m] : (long)m;
    float z = in[r * D_ + threadIdx.x];
#pragma unroll
    for (int p = 1; p < NPART; p++)
        z += in[(long)p * M_ * D_ + r * D_ + threadIdx.x];
    z *= inscale;
    float mean = blockReduceSum256(z) * (1.f / D_);
    float d = z - mean;
    float var = blockReduceSum256(d * d) * (1.f / (D_ - 1));
    float v = d / (sqrtf(var) + EPSF);
    long o = (long)m * D_ + threadIdx.x;
    if (OUT == 1) {
        oh[o] = __half_as_ushort(__float2half_rn(v));
    } else {
        outf[o] = v;
    }
}

// ---------------- launch ----------------
extern "C" void kernel_launch(void* const* d_in, const int* in_sizes, int n_in,
                              void* d_out, int out_size)
{
    (void)in_sizes; (void)n_in; (void)out_size;
    const int*   idx  = (const int*)d_in[0];
    const float* temb = (const float*)d_in[1];
    const float* E    = (const float*)d_in[2];
    const float* Dx   = (const float*)d_in[3];
    const float* Dy   = (const float*)d_in[4];
    float* out = (float*)d_out;

    float *pU, *pS, *pA, *pO;
    __half *pVf, *pDxH, *pDyH, *pEH, *pAf, *pXf, *pYf;
    cudaGetSymbolAddress((void**)&pU,  g_U);
    cudaGetSymbolAddress((void**)&pS,  g_S);
    cudaGetSymbolAddress((void**)&pA,  g_A);
    cudaGetSymbolAddress((void**)&pO,  g_O);
    cudaGetSymbolAddress((void**)&pVf, g_Vf);
    cudaGetSymbolAddress((void**)&pDxH, g_DxH);
    cudaGetSymbolAddress((void**)&pDyH, g_DyH);
    cudaGetSymbolAddress((void**)&pEH, g_EH);
    cudaGetSymbolAddress((void**)&pAf, g_Af);
    cudaGetSymbolAddress((void**)&pXf, g_Xf);
    cudaGetSymbolAddress((void**)&pYf, g_Yf);

    cudaFuncSetAttribute(mma_nt<EPI_RELUH>,
                         cudaFuncAttributeMaxDynamicSharedMemorySize, SMEM_SZ);
    cudaFuncSetAttribute(mma_nt<EPI_NONE>,
                         cudaFuncAttributeMaxDynamicSharedMemorySize, SMEM_SZ);
    cudaFuncSetAttribute(mma_nt<EPI_RELUMULX>,
                         cudaFuncAttributeMaxDynamicSharedMemorySize, SMEM_SZ);

    // fused conversions (+g_DEC)
    conv_all_kernel<<<3072, 256>>>(Dx, Dy, E);
    // embedding gather/convert (+g_CS zero)
    gatherconv_kernel<<<M_, 64>>>(temb, idx);
    // U = LN(emb[idx])
    ln_rows<0, 1><<<M_, 256>>>(temb, pU, nullptr, idx, 1.f);

    // G1 (fp16): 256*P = relu((16v) @ (16Dx)^T) -> g_Yf (fp16), row-sum -> g_CS
    mma_nt<EPI_RELUH><<<dim3(N_ / 256, M_ / 128, 1), 256, SMEM_SZ>>>(
        pVf, pDxH, nullptr, pYf, nullptr,
        N_, D_, D_, 0, 0, 0, 0, 1);

    // scalar L1 recurrence + parallel x scan (on 256-scaled P); emits 256*x fp16
    screc_kernel<<<1, 256>>>();
    xrecur_kernel<<<dim3(N_ / 256, B_, 1), 256>>>();

    // scores (65536*raw, split-K x2, fp16; mask applied downstream in gemm_nn)
    mma_nt<EPI_NONE><<<dim3(T_ / 256, T_ / 128, 2 * B_), 256, SMEM_SZ>>>(
        pXf, pXf, pS, nullptr, nullptr,
        T_, N_, N_ / 2, (long)T_ * N_, (long)T_ * N_, (long)T_ * T_,
        (long)B_ * T_ * T_, B_);

    // a* = (decayed (S0+S1)/65536) @ U  (SIMT fp32, split-K x2; decay+mask+unscale fused)
    gemm_nn<<<dim3(D_ / GBN, T_ / GBM, 2 * B_), 256>>>(
        pS, pS + (long)B_ * T_ * T_, pU, pA);

    // a* <- LN(sum of 2 partials) -> fp16 single
    ln_rows<1, 2><<<M_, 256>>>(pA, nullptr, (unsigned short*)pAf, nullptr, 1.f);

    // G2 (fp16): 1024y = relu(LN(a*) @ (64Dy)^T) * (256x) / 16 -> g_Yf
    mma_nt<EPI_RELUMULX><<<dim3(N_ / 256, M_ / 128, 1), 256, SMEM_SZ>>>(
        pAf, pDyH, nullptr, pYf, pXf,
        N_, D_, D_, 0, 0, 0, 0, 1);

    // G3 (fp16, split-K x2): o_p = (1024y) @ (64E)^T -> g_O partials (65536*o)
    mma_nt<EPI_NONE><<<dim3(D_ / 256, M_ / 128, 2), 256, SMEM_SZ>>>(
        pYf, pEH, pO, nullptr, nullptr,
        D_, N_, N_ / 2, 0, 0, 0, (long)M_ * D_, 1);

    // out = LN((sum of 2 partials) / 65536)
    ln_rows<0, 2><<<M_, 256>>>(pO, out, nullptr, nullptr, 1.f / 65536.f);
}

// round 13
// speedup vs baseline: 1.0815x; 1.0815x over previous
#include <cuda_runtime.h>
#include <cuda_fp16.h>
#include <cstdint>

#define B_   32
#define T_   256
#define N_   4096
#define D_   256
#define M_   (B_ * T_)
#define EPSF 1e-6f
#define DECF 0.97f

// ---------------- scratch (device globals; no allocation) ----------------
__device__ float g_CS[M_];
__device__ float g_Cc[M_];
__device__ float g_U [M_ * D_];
__device__ float g_S [2LL * B_ * T_ * T_];      // 2 split-K partials of 65536*scores
__device__ float g_A [2LL * M_ * D_];           // 2 split-K partials of a*
__device__ float g_O [2LL * M_ * D_];           // 2 split-K partials of G3
__device__ float g_DEC[T_];                     // 0.97^L / 65536 (gemm_nn only)

// fp16 operands; scalings: v,Dx x16; Dy,E x64; P,x x256; y x1024
__device__ __half g_Vf [M_ * D_];                             // 16*emb[idx]
__device__ __half g_DxH[N_ * D_];                             // 16*Dx
__device__ __half g_DyH[N_ * D_];                             // 64*Dy
__device__ __half g_EH [D_ * N_];                             // 64*E
__device__ __half g_Af [M_ * D_];                             // LN(a*) fp16
__device__ __half g_Xf [(long long)M_ * N_];                  // 256*x fp16
__device__ __half g_Yf [(long long)M_ * N_];                  // 256*P, then 1024*y fp16

// ---------------- PTX helpers (baseline ISA only) ----------------
__device__ __forceinline__ uint32_t smem_u32(const void* p) {
    uint32_t a;
    asm("{ .reg .u64 t; cvta.to.shared.u64 t, %1; cvt.u32.u64 %0, t; }" : "=r"(a) : "l"(p));
    return a;
}
__device__ __forceinline__ void cp16(uint32_t so, const void* g) {
    asm volatile("cp.async.cg.shared.global [%0], [%1], 16;" :: "r"(so), "l"(g));
}
__device__ __forceinline__ void cp_commit() {
    asm volatile("cp.async.commit_group;" ::: "memory");
}
template <int NN>
__device__ __forceinline__ void cp_wait() {
    asm volatile("cp.async.wait_group %0;" :: "n"(NN) : "memory");
}
__device__ __forceinline__ void ldsm_x4(uint32_t* f, uint32_t a) {
    asm volatile("ldmatrix.sync.aligned.m8n8.x4.shared.b16 {%0,%1,%2,%3}, [%4];"
        : "=r"(f[0]), "=r"(f[1]), "=r"(f[2]), "=r"(f[3]) : "r"(a));
}
__device__ __forceinline__ void mma_f16(float* c, const uint32_t* a, const uint32_t* b) {
    asm volatile("mma.sync.aligned.m16n8k16.row.col.f32.f16.f16.f32 "
        "{%0,%1,%2,%3}, {%4,%5,%6,%7}, {%8,%9}, {%0,%1,%2,%3};"
        : "+f"(c[0]), "+f"(c[1]), "+f"(c[2]), "+f"(c[3])
        : "r"(a[0]), "r"(a[1]), "r"(a[2]), "r"(a[3]), "r"(b[0]), "r"(b[1]));
}

// -- HMMA NT GEMM: CTA 128x256, warp 64x64, cross-chunk fragment pipelining ----
enum { EPI_NONE = 0, EPI_RELUH = 1, EPI_RELUMULX = 2 };

// swizzled tiles, 64B rows; phys 16B-slot = g ^ ((r>>1)&3)
#define TILE_A  8192                 // 128 rows x 64B
#define TILE_BT 16384                // 256 rows x 64B
#define STAGE_B (TILE_A + TILE_BT)   // 24576
#define NSTG    4
#define SMEM_SZ (NSTG * STAGE_B)     // 98304

template <int EPI>
__global__ void __launch_bounds__(256, 1) mma_nt(
    const __half* __restrict__ Ah, const __half* __restrict__ Bh,
    float* __restrict__ Cf, __half* __restrict__ Ch,
    const __half* __restrict__ Xf,
    int Nd, int K, int kLen, long sA, long sB, long sC, long splitStride, int batches)
{
    extern __shared__ char smem[];
    const uint32_t sb = smem_u32(smem);
    const int tid  = threadIdx.x;
    const int lane = tid & 31;
    const int wid  = tid >> 5;
    const int wm   = wid >> 2;          // 0..1  -> m offset wm*64
    const int wn   = wid & 3;           // 0..3  -> n offset wn*64
    const int zz   = blockIdx.z;
    const int split = zz / batches;
    const int bz    = zz - split * batches;
    const long kOff = (long)split * kLen;
    const int bm = blockIdx.y * 128;
    const int bn = blockIdx.x * 256;

    float acc[4][8][4];
#pragma unroll
    for (int i = 0; i < 4; i++)
#pragma unroll
        for (int j = 0; j < 8; j++)
#pragma unroll
            for (int v = 0; v < 4; v++) acc[i][j][v] = 0.f;

    {
        const __half* Ahp = Ah + (long)bz * sA + (long)bm * K + kOff;
        const __half* Bhp = Bh + (long)bz * sB + (long)bn * K + kOff;

        const int qr0 = tid >> 2;             // row (0..63)
        const int qc0 = tid & 3;              // 16B group
        auto stage_load = [&](int stg, int k0) {
            uint32_t base = sb + stg * STAGE_B;
#pragma unroll
            for (int i = 0; i < 2; i++) {     // A: 128 rows
                int r = qr0 + i * 64;
                uint32_t so = (uint32_t)(r * 64 + ((qc0 ^ ((r >> 1) & 3)) * 16));
                cp16(base + so, Ahp + (long)r * K + k0 + qc0 * 8);
            }
#pragma unroll
            for (int i = 0; i < 4; i++) {     // B: 256 rows
                int r = qr0 + i * 64;
                uint32_t so = (uint32_t)(r * 64 + ((qc0 ^ ((r >> 1) & 3)) * 16));
                cp16(base + TILE_A + so, Bhp + (long)r * K + k0 + qc0 * 8);
            }
            cp_commit();
        };

        const int nC = kLen / 32;             // all callers have nC >= 8
        stage_load(0, 0);
        stage_load(1, 32);
        stage_load(2, 64);

        // per-lane ldsm logical positions
        const uint32_t aRow  = (uint32_t)(wm * 64 + (lane & 15));
        const uint32_t aColG = (uint32_t)(lane >> 4);
        const uint32_t bRow  = (uint32_t)(wn * 64 + ((lane >> 4) << 3) + (lane & 7));
        const uint32_t bColG = (uint32_t)((lane >> 3) & 1);
        const uint32_t sa  = (aRow >> 1) & 3;
        const uint32_t sbw = (bRow >> 1) & 3;
        uint32_t aoff[2], boff[2];
#pragma unroll
        for (int ks = 0; ks < 2; ks++) {
            aoff[ks] = aRow * 64 + (((ks * 2 + aColG) ^ sa) * 16);
            boff[ks] = bRow * 64 + (((ks * 2 + bColG) ^ sbw) * 16);
        }

        // fragment ping-pong buffers
        uint32_t fA0[4][4], fB0[4][4], fA1[4][4], fB1[4][4];

        // prologue: stage 0 ready -> preload chunk0 ks0 fragments
        cp_wait<2>();
        __syncthreads();
#pragma unroll
        for (int ma = 0; ma < 4; ma++)
            ldsm_x4(fA0[ma], sb + aoff[0] + ma * 1024);
#pragma unroll
        for (int p = 0; p < 4; p++)
            ldsm_x4(fB0[p], sb + TILE_A + boff[0] + p * 1024);

        int stg = 0;
        for (int c = 0; c < nC; c++) {
            // all warps finished reading stage (c-1) during iteration c-1
            __syncthreads();
            if (c + 3 < nC) {
                int ns = stg + 3; if (ns >= NSTG) ns -= NSTG;
                stage_load(ns, (c + 3) * 32);
            } else {
                cp_commit();   // empty group keeps wait accounting uniform
            }

            const uint32_t st = sb + stg * STAGE_B;
            // issue ks1 fragment loads (LSU) ...
#pragma unroll
            for (int ma = 0; ma < 4; ma++)
                ldsm_x4(fA1[ma], st + aoff[1] + ma * 1024);
#pragma unroll
            for (int p = 0; p < 4; p++)
                ldsm_x4(fB1[p], st + TILE_A + boff[1] + p * 1024);
            // ... while tensor pipe crunches the preloaded ks0 fragments
#pragma unroll
            for (int ma = 0; ma < 4; ma++)
#pragma unroll
                for (int na = 0; na < 8; na++)
                    mma_f16(acc[ma][na], fA0[ma], &fB0[na >> 1][2 * (na & 1)]);

            // stage c+1 is complete (issued 3 chunks ago); prefetch its ks0 frags
            cp_wait<2>();
            int nstg = stg + 1; if (nstg >= NSTG) nstg = 0;
            if (c + 1 < nC) {
                const uint32_t st2 = sb + nstg * STAGE_B;
#pragma unroll
                for (int ma = 0; ma < 4; ma++)
                    ldsm_x4(fA0[ma], st2 + aoff[0] + ma * 1024);
#pragma unroll
                for (int p = 0; p < 4; p++)
                    ldsm_x4(fB0[p], st2 + TILE_A + boff[0] + p * 1024);
            }
#pragma unroll
            for (int ma = 0; ma < 4; ma++)
#pragma unroll
                for (int na = 0; na < 8; na++)
                    mma_f16(acc[ma][na], fA1[ma], &fB1[na >> 1][2 * (na & 1)]);

            stg = nstg;
        }
    }

    // ---- epilogue ----
    float* Cfo = (EPI == EPI_NONE) ? (Cf + split * splitStride + (long)bz * sC) : nullptr;
    unsigned short* Ho = (EPI != EPI_NONE) ? reinterpret_cast<unsigned short*>(Ch) : nullptr;
    const int gr = lane >> 2;          // 0..7
    const int gc = (lane & 3) * 2;
#pragma unroll
    for (int ma = 0; ma < 4; ma++) {
#pragma unroll
        for (int half = 0; half < 2; half++) {
            const int row = bm + wm * 64 + ma * 16 + gr + half * 8;
            float rs = 0.f;
#pragma unroll
            for (int na = 0; na < 8; na++) {
                const int col = bn + wn * 64 + na * 8 + gc;
                float v0 = acc[ma][na][half * 2 + 0];
                float v1 = acc[ma][na][half * 2 + 1];
                long off = (long)row * Nd + col;
                if (EPI == EPI_RELUH) {
                    // 256*P = relu(acc); fused row-sum (of 256*P) for L1 norm
                    v0 = fmaxf(v0, 0.f); v1 = fmaxf(v1, 0.f);
                    rs += v0 + v1;
                    ushort2 o = make_ushort2(__half_as_ushort(__float2half_rn(v0)),
                                             __half_as_ushort(__float2half_rn(v1)));
                    *reinterpret_cast<ushort2*>(Ho + off) = o;
                } else if (EPI == EPI_RELUMULX) {
                    // stored y = relu(64g) * (256x) / 16 = 1024*y_true
                    ushort2 xf = *reinterpret_cast<const ushort2*>(Xf + off);
                    float x0 = __half2float(__ushort_as_half(xf.x));
                    float x1 = __half2float(__ushort_as_half(xf.y));
                    v0 = fmaxf(v0, 0.f) * x0 * (1.f / 16.f);
                    v1 = fmaxf(v1, 0.f) * x1 * (1.f / 16.f);
                    ushort2 o = make_ushort2(__half_as_ushort(__float2half_rn(v0)),
                                             __half_as_ushort(__float2half_rn(v1)));
                    *reinterpret_cast<ushort2*>(Ho + off) = o;
                } else {
                    *reinterpret_cast<float2*>(Cfo + off) = make_float2(v0, v1);
                }
            }
            if (EPI == EPI_RELUH) {
                rs += __shfl_xor_sync(0xffffffffu, rs, 1);
                rs += __shfl_xor_sync(0xffffffffu, rs, 2);
                if ((lane & 3) == 0) atomicAdd(&g_CS[row], rs);
            }
        }
    }
}

// ---------------- SIMT NN GEMM: a* = (decayed S) @ U, split-K x2 ----------------
#define GBM 128
#define GBN 64
#define GBK 16
#define GTM 8
#define GTN 4

__global__ __launch_bounds__(256)
void gemm_nn(const float* __restrict__ A0, const float* __restrict__ A1,
             const float* __restrict__ B, float* __restrict__ C)
{
    const int zz = blockIdx.z;
    const int bz = zz & 31;          // batch
    const int split = zz >> 5;       // 0..1
    A0 += (long)bz * T_ * T_;
    A1 += (long)bz * T_ * T_;
    B  += (long)bz * T_ * D_;
    C  += (long)split * M_ * D_ + (long)bz * T_ * D_;
    const int bm = blockIdx.y * GBM;
    const int bn = blockIdx.x * GBN;

    __shared__ __align__(16) float As[GBK][GBM + 4];
    __shared__ __align__(16) float Bs[GBK][GBN + 4];

    const int tid = threadIdx.x;
    const int tx = tid & 15;
    const int ty = tid >> 4;

    float acc[GTM][GTN];
#pragma unroll
    for (int i = 0; i < GTM; i++)
#pragma unroll
        for (int j = 0; j < GTN; j++) acc[i][j] = 0.f;

    const int lr = tid >> 2;
    const int lk = (tid & 3) * 4;
    const int brow = tid >> 4;
    const int bcol = (tid & 15) * 4;

    const int kBeg = split * (T_ / 2);
    for (int k0 = kBeg; k0 < kBeg + T_ / 2; k0 += GBK) {
#pragma unroll
        for (int i = 0; i < 2; i++) {
            int r = lr + i * 64;
            int t = bm + r;
            long ao = (long)t * T_ + k0 + lk;
            float4 v = *reinterpret_cast<const float4*>(A0 + ao);
            float4 w = *reinterpret_cast<const float4*>(A1 + ao);
            float vv[4] = {v.x + w.x, v.y + w.y, v.z + w.z, v.w + w.w};
#pragma unroll
            for (int j = 0; j < 4; j++) {
                int L = t - (k0 + lk + j);
                As[lk + j][r] = (L > 0) ? vv[j] * g_DEC[L] : 0.f;   // /65536 baked into g_DEC
            }
        }
        {
            float4 v = *reinterpret_cast<const float4*>(B + (long)(k0 + brow) * D_ + bn + bcol);
            Bs[brow][bcol + 0] = v.x; Bs[brow][bcol + 1] = v.y;
            Bs[brow][bcol + 2] = v.z; Bs[brow][bcol + 3] = v.w;
        }
        __syncthreads();
#pragma unroll
        for (int kk = 0; kk < GBK; kk++) {
            float af[GTM], bf[GTN];
#pragma unroll
            for (int i = 0; i < GTM; i++) af[i] = As[kk][ty * GTM + i];
#pragma unroll
            for (int j = 0; j < GTN; j++) bf[j] = Bs[kk][tx * GTN + j];
#pragma unroll
            for (int i = 0; i < GTM; i++)
#pragma unroll
                for (int j = 0; j < GTN; j++)
                    acc[i][j] = fmaf(af[i], bf[j], acc[i][j]);
        }
        __syncthreads();
    }
#pragma unroll
    for (int i = 0; i < GTM; i++) {
        int row = bm + ty * GTM + i;
        long cbase = (long)row * D_ + bn + tx * GTN;
        *reinterpret_cast<float4*>(C + cbase) = make_float4(acc[i][0], acc[i][1], acc[i][2], acc[i][3]);
    }
}

// ---------------- elementwise / scan / LN kernels ----------------
__device__ __forceinline__ float blockReduceSum256(float v) {
    __shared__ float sh[8];
    __syncthreads();
    int lane = threadIdx.x & 31;
    int w = threadIdx.x >> 5;
#pragma unroll
    for (int o = 16; o > 0; o >>= 1) v += __shfl_down_sync(0xffffffffu, v, o);
    if (lane == 0) sh[w] = v;
    __syncthreads();
    if (w == 0) {
        float t = (lane < 8) ? sh[lane] : 0.f;
#pragma unroll
        for (int o = 4; o > 0; o >>= 1) t += __shfl_down_sync(0xffffffffu, t, o);
        if (lane == 0) sh[0] = t;
    }
    __syncthreads();
    return sh[0];
}

// fused conversions: Dx x16, Dy x64, E x64 -> fp16 single; + g_DEC init
__global__ void conv_all_kernel(const float* __restrict__ Dx, const float* __restrict__ Dy,
                                const float* __restrict__ E)
{
    int blk = blockIdx.x;
    const float* src;
    __half* hi;
    float scale;
    int local;
    if (blk < 1024)      { src = Dx; hi = g_DxH; scale = 16.f; local = blk; }
    else if (blk < 2048) { src = Dy; hi = g_DyH; scale = 64.f; local = blk - 1024; }
    else                 { src = E;  hi = g_EH;  scale = 64.f; local = blk - 2048; }
    long i = (long)local * 256 + threadIdx.x;
    float4 v = reinterpret_cast<const float4*>(src)[i];
    ushort4 o = make_ushort4(
        __half_as_ushort(__float2half_rn(v.x * scale)),
        __half_as_ushort(__float2half_rn(v.y * scale)),
        __half_as_ushort(__float2half_rn(v.z * scale)),
        __half_as_ushort(__float2half_rn(v.w * scale)));
    reinterpret_cast<ushort4*>(hi)[i] = o;
    if (blk == 0 && threadIdx.x == 0) {
        float d = 1.f;
        for (int t = 0; t < T_; t++) { g_DEC[t] = d * (1.f / 65536.f); d *= DECF; }
    }
}

// gather 16*emb[idx] -> fp16 single, and zero g_CS
__global__ void gatherconv_kernel(const float* __restrict__ emb, const int* __restrict__ idx)
{
    int m = blockIdx.x;
    int t = threadIdx.x;   // 64 threads, float4 each
    if (t == 0) g_CS[m] = 0.f;
    float4 v = *reinterpret_cast<const float4*>(emb + (long)idx[m] * D_ + t * 4);
    ushort4 o = make_ushort4(
        __half_as_ushort(__float2half_rn(v.x * 16.f)),
        __half_as_ushort(__float2half_rn(v.y * 16.f)),
        __half_as_ushort(__float2half_rn(v.z * 16.f)),
        __half_as_ushort(__float2half_rn(v.w * 16.f)));
    reinterpret_cast<ushort4*>(g_Vf)[(long)m * (D_ / 4) + t] = o;
}

__global__ void screc_kernel() {
    __shared__ float cs[B_ * T_];     // [t][b] layout, conflict-free
    for (int i = threadIdx.x; i < B_ * T_; i += 256) {
        int t = i >> 5, b = i & 31;
        cs[t * 32 + b] = g_CS[b * T_ + t] * (1.f / 256.f);   // unscale 256*P
    }
    __syncthreads();
    if (threadIdx.x < B_) {
        int b = threadIdx.x;
        float sprev = 0.f;
        for (int t = 0; t < T_; t++) {
            float sumx = __fdividef(sprev, sprev + EPSF);
            float s = DECF * sumx + cs[t * 32 + b];
            g_Cc[b * T_ + t] = __fdividef(1.f, s + EPSF);
            sprev = s;
        }
    }
}

// scan on 256-scaled values (linear in scale): X = 256*x
__global__ void xrecur_kernel() {
    int b = blockIdx.y;
    int n = blockIdx.x * 256 + threadIdx.x;
    __shared__ float sc[T_];
    sc[threadIdx.x] = g_Cc[b * T_ + threadIdx.x];
    __syncthreads();
    float X = 0.f;
    long base = (long)b * T_ * N_ + n;
    for (int t = 0; t < T_; t++) {
        float p = __half2float(g_Yf[base + (long)t * N_]);    // 256*P
        X = (DECF * X + p) * sc[t];
        g_Xf[base + (long)t * N_] = __float2half_rn(X);
    }
}

// OUT: 0 = fp32, 1 = fp16 single
template <int OUT, int NPART>
__global__ void ln_rows(const float* __restrict__ in, float* __restrict__ outf,
                        unsigned short* __restrict__ oh,
                        const int* __restrict__ gidx, float inscale)
{
    int m = blockIdx.x;
    long r = gidx ? (long)gidx[m] : (long)m;
    float z = in[r * D_ + threadIdx.x];
#pragma unroll
    for (int p = 1; p < NPART; p++)
        z += in[(long)p * M_ * D_ + r * D_ + threadIdx.x];
    z *= inscale;
    float mean = blockReduceSum256(z) * (1.f / D_);
    float d = z - mean;
    float var = blockReduceSum256(d * d) * (1.f / (D_ - 1));
    float v = d / (sqrtf(var) + EPSF);
    long o = (long)m * D_ + threadIdx.x;
    if (OUT == 1) {
        oh[o] = __half_as_ushort(__float2half_rn(v));
    } else {
        outf[o] = v;
    }
}

// ---------------- launch ----------------
extern "C" void kernel_launch(void* const* d_in, const int* in_sizes, int n_in,
                              void* d_out, int out_size)
{
    (void)in_sizes; (void)n_in; (void)out_size;
    const int*   idx  = (const int*)d_in[0];
    const float* temb = (const float*)d_in[1];
    const float* E    = (const float*)d_in[2];
    const float* Dx   = (const float*)d_in[3];
    const float* Dy   = (const float*)d_in[4];
    float* out = (float*)d_out;

    float *pU, *pS, *pA, *pO;
    __half *pVf, *pDxH, *pDyH, *pEH, *pAf, *pXf, *pYf;
    cudaGetSymbolAddress((void**)&pU,  g_U);
    cudaGetSymbolAddress((void**)&pS,  g_S);
    cudaGetSymbolAddress((void**)&pA,  g_A);
    cudaGetSymbolAddress((void**)&pO,  g_O);
    cudaGetSymbolAddress((void**)&pVf, g_Vf);
    cudaGetSymbolAddress((void**)&pDxH, g_DxH);
    cudaGetSymbolAddress((void**)&pDyH, g_DyH);
    cudaGetSymbolAddress((void**)&pEH, g_EH);
    cudaGetSymbolAddress((void**)&pAf, g_Af);
    cudaGetSymbolAddress((void**)&pXf, g_Xf);
    cudaGetSymbolAddress((void**)&pYf, g_Yf);

    cudaFuncSetAttribute(mma_nt<EPI_RELUH>,
                         cudaFuncAttributeMaxDynamicSharedMemorySize, SMEM_SZ);
    cudaFuncSetAttribute(mma_nt<EPI_NONE>,
                         cudaFuncAttributeMaxDynamicSharedMemorySize, SMEM_SZ);
    cudaFuncSetAttribute(mma_nt<EPI_RELUMULX>,
                         cudaFuncAttributeMaxDynamicSharedMemorySize, SMEM_SZ);

    // fused conversions (+g_DEC)
    conv_all_kernel<<<3072, 256>>>(Dx, Dy, E);
    // embedding gather/convert (+g_CS zero)
    gatherconv_kernel<<<M_, 64>>>(temb, idx);
    // U = LN(emb[idx])
    ln_rows<0, 1><<<M_, 256>>>(temb, pU, nullptr, idx, 1.f);

    // G1 (fp16): 256*P = relu((16v) @ (16Dx)^T) -> g_Yf (fp16), row-sum -> g_CS
    mma_nt<EPI_RELUH><<<dim3(N_ / 256, M_ / 128, 1), 256, SMEM_SZ>>>(
        pVf, pDxH, nullptr, pYf, nullptr,
        N_, D_, D_, 0, 0, 0, 0, 1);

    // scalar L1 recurrence + parallel x scan (on 256-scaled P); emits 256*x fp16
    screc_kernel<<<1, 256>>>();
    xrecur_kernel<<<dim3(N_ / 256, B_, 1), 256>>>();

    // scores (65536*raw, split-K x2, fp16; mask applied downstream in gemm_nn)
    mma_nt<EPI_NONE><<<dim3(T_ / 256, T_ / 128, 2 * B_), 256, SMEM_SZ>>>(
        pXf, pXf, pS, nullptr, nullptr,
        T_, N_, N_ / 2, (long)T_ * N_, (long)T_ * N_, (long)T_ * T_,
        (long)B_ * T_ * T_, B_);

    // a* = (decayed (S0+S1)/65536) @ U  (SIMT fp32, split-K x2; decay+mask+unscale fused)
    gemm_nn<<<dim3(D_ / GBN, T_ / GBM, 2 * B_), 256>>>(
        pS, pS + (long)B_ * T_ * T_, pU, pA);

    // a* <- LN(sum of 2 partials) -> fp16 single
    ln_rows<1, 2><<<M_, 256>>>(pA, nullptr, (unsigned short*)pAf, nullptr, 1.f);

    // G2 (fp16): 1024y = relu(LN(a*) @ (64Dy)^T) * (256x) / 16 -> g_Yf
    mma_nt<EPI_RELUMULX><<<dim3(N_ / 256, M_ / 128, 1), 256, SMEM_SZ>>>(
        pAf, pDyH, nullptr, pYf, pXf,
        N_, D_, D_, 0, 0, 0, 0, 1);

    // G3 (fp16, split-K x2): o_p = (1024y) @ (64E)^T -> g_O partials (65536*o)
    mma_nt<EPI_NONE><<<dim3(D_ / 256, M_ / 128, 2), 256, SMEM_SZ>>>(
        pYf, pEH, pO, nullptr, nullptr,
        D_, N_, N_ / 2, 0, 0, 0, (long)M_ * D_, 1);

    // out = LN((sum of 2 partials) / 65536)
    ln_rows<0, 2><<<M_, 256>>>(pO, out, nullptr, nullptr, 1.f / 65536.f);
}